// round 2
// baseline (speedup 1.0000x reference)
#include <cuda_runtime.h>
#include <cuda_bf16.h>

#define IN_FEATURES  256
#define OUT_FEATURES 4096
#define BATCH        8192

// Scratch: per-out-feature source index (derived from expansion_mapping each call).
__device__ int g_src_idx[OUT_FEATURES];

// Prologue: src[j] = argmax_i E[j, i]  (E is one-hot rows, 4096 x 256)
__global__ void build_src_idx_kernel(const float* __restrict__ em) {
    int j = blockIdx.x * blockDim.x + threadIdx.x;
    if (j >= OUT_FEATURES) return;
    const float* row = em + (size_t)j * IN_FEATURES;
    int best = 0;
    float bv = row[0];
    #pragma unroll 8
    for (int i = 1; i < IN_FEATURES; i++) {
        float v = __ldg(&row[i]);
        if (v > bv) { bv = v; best = i; }
    }
    g_src_idx[j] = best;
}

// Main: out[b, j] = exp(-0.5 * z^2) * coefs[j],  z = (x[b, src[j]] - means[j]) / vars[j]
// One thread per float4 of output. B*OUT/4 = 8,388,608 threads.
__global__ __launch_bounds__(256) void urbf_kernel(
    const float* __restrict__ x,
    const float* __restrict__ means,
    const float* __restrict__ vars_,
    const float* __restrict__ coefs,
    float* __restrict__ out)
{
    int tid = blockIdx.x * blockDim.x + threadIdx.x;          // [0, B*OUT/4)
    int j4  = tid & (OUT_FEATURES / 4 - 1);                   // float4 index within row
    int b   = tid >> 10;                                      // OUT/4 = 1024
    int j   = j4 * 4;

    int4 src = *reinterpret_cast<const int4*>(&g_src_idx[j]);

    const float* xrow = x + (size_t)b * IN_FEATURES;
    float v0 = __ldg(&xrow[src.x]);
    float v1 = __ldg(&xrow[src.y]);
    float v2 = __ldg(&xrow[src.z]);
    float v3 = __ldg(&xrow[src.w]);

    float4 m = __ldg(reinterpret_cast<const float4*>(&means[j]));
    float4 s = __ldg(reinterpret_cast<const float4*>(&vars_[j]));
    float4 c = __ldg(reinterpret_cast<const float4*>(&coefs[j]));

    float z0 = __fdividef(v0 - m.x, s.x);
    float z1 = __fdividef(v1 - m.y, s.y);
    float z2 = __fdividef(v2 - m.z, s.z);
    float z3 = __fdividef(v3 - m.w, s.w);

    float4 o;
    o.x = __expf(-0.5f * z0 * z0) * c.x;
    o.y = __expf(-0.5f * z1 * z1) * c.y;
    o.z = __expf(-0.5f * z2 * z2) * c.z;
    o.w = __expf(-0.5f * z3 * z3) * c.w;

    *reinterpret_cast<float4*>(&out[(size_t)b * OUT_FEATURES + j]) = o;
}

extern "C" void kernel_launch(void* const* d_in, const int* in_sizes, int n_in,
                              void* d_out, int out_size) {
    const float* x     = (const float*)d_in[0];  // [8192, 256]
    const float* em    = (const float*)d_in[1];  // [4096, 256]
    const float* means = (const float*)d_in[2];  // [4096]
    const float* vars_ = (const float*)d_in[3];  // [4096]
    const float* coefs = (const float*)d_in[4];  // [4096]
    float* out = (float*)d_out;                  // [8192, 4096]

    build_src_idx_kernel<<<(OUT_FEATURES + 255) / 256, 256>>>(em);

    const int total4 = BATCH * OUT_FEATURES / 4;             // 8,388,608
    urbf_kernel<<<total4 / 256, 256>>>(x, means, vars_, coefs, out);
}

// round 3
// speedup vs baseline: 1.8258x; 1.8258x over previous
#include <cuda_runtime.h>
#include <cuda_bf16.h>

#define IN_FEATURES  256
#define OUT_FEATURES 4096
#define BATCH        8192

// Packed per-out-feature params: {mean, inv_var, coef, src_index_as_bits}
__device__ float4 g_table[OUT_FEATURES];

// Prologue: one thread per (j,i) element of expansion_mapping (4096x256 = 1M threads).
// Coalesced read; only the one-hot "hit" threads (4096 of them) build the table entry.
__global__ void build_table_kernel(const float* __restrict__ em,
                                   const float* __restrict__ means,
                                   const float* __restrict__ vars_,
                                   const float* __restrict__ coefs) {
    int tid = blockIdx.x * blockDim.x + threadIdx.x;   // [0, OUT*IN)
    int i = tid & (IN_FEATURES - 1);
    int j = tid >> 8;                                   // IN_FEATURES = 256
    if (em[tid] > 0.5f) {
        float4 t;
        t.x = __ldg(&means[j]);
        t.y = 1.0f / __ldg(&vars_[j]);
        t.z = __ldg(&coefs[j]);
        t.w = __int_as_float(i);
        g_table[j] = t;
    }
}

// Main: out[b, j] = exp(-0.5*z^2)*coef,  z = (x[b,src[j]] - mean[j]) * inv_var[j]
// Each thread: 4 consecutive j's x 4 consecutive batch rows (table loaded once).
__global__ __launch_bounds__(256) void urbf_kernel(
    const float* __restrict__ x,
    float* __restrict__ out)
{
    int tid = blockIdx.x * blockDim.x + threadIdx.x;   // [0, (B/4)*(OUT/4))
    int j4  = tid & (OUT_FEATURES / 4 - 1);            // 0..1023
    int bg  = tid >> 10;                               // 0..2047 (4 rows each)
    int j   = j4 * 4;

    float4 t0 = g_table[j + 0];
    float4 t1 = g_table[j + 1];
    float4 t2 = g_table[j + 2];
    float4 t3 = g_table[j + 3];
    int s0 = __float_as_int(t0.w);
    int s1 = __float_as_int(t1.w);
    int s2 = __float_as_int(t2.w);
    int s3 = __float_as_int(t3.w);

    const float* xbase = x + (size_t)bg * 4 * IN_FEATURES;
    float* obase = out + (size_t)bg * 4 * OUT_FEATURES + j;

    #pragma unroll
    for (int r = 0; r < 4; r++) {
        const float* xr = xbase + r * IN_FEATURES;
        float v0 = __ldg(xr + s0);
        float v1 = __ldg(xr + s1);
        float v2 = __ldg(xr + s2);
        float v3 = __ldg(xr + s3);

        float z0 = (v0 - t0.x) * t0.y;
        float z1 = (v1 - t1.x) * t1.y;
        float z2 = (v2 - t2.x) * t2.y;
        float z3 = (v3 - t3.x) * t3.y;

        float4 o;
        o.x = __expf(-0.5f * z0 * z0) * t0.z;
        o.y = __expf(-0.5f * z1 * z1) * t1.z;
        o.z = __expf(-0.5f * z2 * z2) * t2.z;
        o.w = __expf(-0.5f * z3 * z3) * t3.z;

        *reinterpret_cast<float4*>(obase + (size_t)r * OUT_FEATURES) = o;
    }
}

extern "C" void kernel_launch(void* const* d_in, const int* in_sizes, int n_in,
                              void* d_out, int out_size) {
    const float* x     = (const float*)d_in[0];  // [8192, 256]
    const float* em    = (const float*)d_in[1];  // [4096, 256]
    const float* means = (const float*)d_in[2];  // [4096]
    const float* vars_ = (const float*)d_in[3];  // [4096]
    const float* coefs = (const float*)d_in[4];  // [4096]
    float* out = (float*)d_out;                  // [8192, 4096]

    const int em_elems = OUT_FEATURES * IN_FEATURES;         // 1,048,576
    build_table_kernel<<<em_elems / 256, 256>>>(em, means, vars_, coefs);

    const int total = (BATCH / 4) * (OUT_FEATURES / 4);      // 2,097,152
    urbf_kernel<<<total / 256, 256>>>(x, out);
}

// round 5
// speedup vs baseline: 2.6730x; 1.4640x over previous
#include <cuda_runtime.h>
#include <cuda_bf16.h>

#define IN_FEATURES  256
#define OUT_FEATURES 4096
#define BATCH        8192

#define J_PER_CTA    1024   // 256 threads x 4 j
#define R_PER_CTA    8      // batch rows per CTA

// Packed per-out-feature params: {mean, inv_var, coef, src_index_as_bits}
__device__ float4 g_table[OUT_FEATURES];

// Prologue: one thread per float4 of expansion_mapping (4096x256/4 = 256K threads).
__global__ void build_table_kernel(const float4* __restrict__ em4,
                                   const float* __restrict__ means,
                                   const float* __restrict__ vars_,
                                   const float* __restrict__ coefs) {
    int tid = blockIdx.x * blockDim.x + threadIdx.x;    // [0, OUT*IN/4)
    float4 e = em4[tid];
    int base_i = (tid & (IN_FEATURES / 4 - 1)) * 4;
    int j = tid >> 6;                                    // IN_FEATURES/4 = 64
    int hit = -1;
    if (e.x > 0.5f) hit = base_i + 0;
    if (e.y > 0.5f) hit = base_i + 1;
    if (e.z > 0.5f) hit = base_i + 2;
    if (e.w > 0.5f) hit = base_i + 3;
    if (hit >= 0) {
        float4 t;
        t.x = __ldg(&means[j]);
        t.y = 1.0f / __ldg(&vars_[j]);
        t.z = __ldg(&coefs[j]);
        t.w = __int_as_float(hit);
        g_table[j] = t;
    }
}

// Main: out[b, j] = exp(-0.5*z^2)*coef,  z = (x[b,src[j]] - mean[j]) * inv_var[j]
// CTA: 256 threads, 1024 consecutive j (4/thread), 8 consecutive batch rows.
__global__ __launch_bounds__(256) void urbf_kernel(
    const float* __restrict__ x,
    float* __restrict__ out)
{
    int jblk = blockIdx.x & 3;                 // 4 j-blocks of 1024
    int rblk = blockIdx.x >> 2;                // 1024 row-blocks of 8
    int j = jblk * J_PER_CTA + threadIdx.x * 4;

    float4 t0 = g_table[j + 0];
    float4 t1 = g_table[j + 1];
    float4 t2 = g_table[j + 2];
    float4 t3 = g_table[j + 3];
    int s0 = __float_as_int(t0.w);
    int s1 = __float_as_int(t1.w);
    int s2 = __float_as_int(t2.w);
    int s3 = __float_as_int(t3.w);
    bool uni = (s0 == s1) && (s1 == s2) && (s2 == s3);

    const float* xbase = x + (size_t)rblk * R_PER_CTA * IN_FEATURES;
    float* obase = out + (size_t)rblk * R_PER_CTA * OUT_FEATURES + j;

    #pragma unroll
    for (int r = 0; r < R_PER_CTA; r++) {
        const float* xr = xbase + r * IN_FEATURES;
        float v0, v1, v2, v3;
        if (uni) {
            v0 = __ldg(xr + s0);
            v1 = v0; v2 = v0; v3 = v0;
        } else {
            v0 = __ldg(xr + s0);
            v1 = __ldg(xr + s1);
            v2 = __ldg(xr + s2);
            v3 = __ldg(xr + s3);
        }

        float z0 = (v0 - t0.x) * t0.y;
        float z1 = (v1 - t1.x) * t1.y;
        float z2 = (v2 - t2.x) * t2.y;
        float z3 = (v3 - t3.x) * t3.y;

        float4 o;
        o.x = __expf(-0.5f * z0 * z0) * t0.z;
        o.y = __expf(-0.5f * z1 * z1) * t1.z;
        o.z = __expf(-0.5f * z2 * z2) * t2.z;
        o.w = __expf(-0.5f * z3 * z3) * t3.z;

        __stcs(reinterpret_cast<float4*>(obase + (size_t)r * OUT_FEATURES), o);
    }
}

extern "C" void kernel_launch(void* const* d_in, const int* in_sizes, int n_in,
                              void* d_out, int out_size) {
    const float* x     = (const float*)d_in[0];  // [8192, 256]
    const float* em    = (const float*)d_in[1];  // [4096, 256]
    const float* means = (const float*)d_in[2];  // [4096]
    const float* vars_ = (const float*)d_in[3];  // [4096]
    const float* coefs = (const float*)d_in[4];  // [4096]
    float* out = (float*)d_out;                  // [8192, 4096]

    const int em_vec4 = OUT_FEATURES * IN_FEATURES / 4;      // 262,144
    build_table_kernel<<<em_vec4 / 256, 256>>>(
        (const float4*)em, means, vars_, coefs);

    const int nblocks = (OUT_FEATURES / J_PER_CTA) * (BATCH / R_PER_CTA);  // 4096
    urbf_kernel<<<nblocks, 256>>>(x, out);
}